// round 1
// baseline (speedup 1.0000x reference)
#include <cuda_runtime.h>

#define FFT_M    4096   // complex FFT size (= d/2)
#define NREAL    8192   // sketch / output dim d
#define NTHREADS 512
#define IMG_DIM  2048
#define TXT_DIM  768

__device__ __forceinline__ float2 cadd(float2 a, float2 b){ return make_float2(a.x+b.x, a.y+b.y); }
__device__ __forceinline__ float2 csub(float2 a, float2 b){ return make_float2(a.x-b.x, a.y-b.y); }
__device__ __forceinline__ float2 cmul(float2 a, float2 b){
    return make_float2(fmaf(a.x, b.x, -a.y*b.y), fmaf(a.x, b.y, a.y*b.x));
}

// Radix-4 Stockham autosort FFT, size 4096, in shared memory.
// DIR = -1 forward (e^{-i...}), +1 inverse (unnormalized).
// Ping-pongs x <-> tmp; 6 stages (even) => result ends back in x.
// Ends with __syncthreads().
template<int DIR>
__device__ void fft4096(float2* __restrict__ x, float2* __restrict__ tmp, int tid) {
    float2* in  = x;
    float2* out = tmp;
    #pragma unroll
    for (int stage = 0; stage < 6; stage++) {
        const int Ns = 1 << (2 * stage);
        const float ang_scale = (float)DIR * 6.2831853071795864f / (4.0f * (float)Ns);
        #pragma unroll
        for (int j = tid; j < FFT_M/4; j += NTHREADS) {
            int m    = j & (Ns - 1);
            int base = ((j - m) << 2) + m;   // (j/Ns)*4Ns + m
            float2 v0 = in[j];
            float2 v1 = in[j +   FFT_M/4];
            float2 v2 = in[j +   FFT_M/2];
            float2 v3 = in[j + 3*FFT_M/4];
            float s, c;
            __sincosf(ang_scale * (float)m, &s, &c);
            float2 w1 = make_float2(c, s);
            float2 w2 = cmul(w1, w1);
            float2 w3 = cmul(w2, w1);
            v1 = cmul(v1, w1);
            v2 = cmul(v2, w2);
            v3 = cmul(v3, w3);
            float2 t0 = cadd(v0, v2), t1 = csub(v0, v2);
            float2 t2 = cadd(v1, v3), t3 = csub(v1, v3);
            // fwd: y1 = t1 - i t3, y3 = t1 + i t3 ; inv: swapped
            float2 jt3 = (DIR < 0) ? make_float2(t3.y, -t3.x)
                                   : make_float2(-t3.y, t3.x);
            out[base]          = cadd(t0, t2);
            out[base +   Ns]   = cadd(t1, jt3);
            out[base + 2*Ns]   = csub(t0, t2);
            out[base + 3*Ns]   = csub(t1, jt3);
        }
        __syncthreads();
        float2* sw = in; in = out; out = sw;
    }
}

__global__ void __launch_bounds__(NTHREADS)
bilinear_fusion_kernel(
    const float* __restrict__ img,  const float* __restrict__ txt,
    const int*   __restrict__ h1,   const int*   __restrict__ h2,
    const float* __restrict__ s1,   const float* __restrict__ s2,
    const float* __restrict__ gamma,const float* __restrict__ beta,
    float* __restrict__ out)
{
    extern __shared__ float2 sm[];
    float2* A = sm;              // sketch1 -> Z1
    float2* B = sm +   FFT_M;    // FFT scratch -> ZY -> y
    float2* C = sm + 2*FFT_M;    // sketch2 -> Z2
    __shared__ float rs[16], rq[16];

    const int b   = blockIdx.x;
    const int tid = threadIdx.x;

    // ---- count sketches (scatter-add into smem) ----
    float* rA = (float*)A;
    float* rC = (float*)C;
    for (int i = tid; i < NREAL; i += NTHREADS) { rA[i] = 0.0f; rC[i] = 0.0f; }
    __syncthreads();

    const float* irow = img + (size_t)b * IMG_DIM;
    for (int i = tid; i < IMG_DIM; i += NTHREADS)
        atomicAdd(&rA[h1[i]], irow[i] * s1[i]);
    const float* trow = txt + (size_t)b * TXT_DIM;
    for (int i = tid; i < TXT_DIM; i += NTHREADS)
        atomicAdd(&rC[h2[i]], trow[i] * s2[i]);
    __syncthreads();

    // ---- forward FFTs of the packed real signals ----
    fft4096<-1>(A, B, tid);   // Z1 = DFT_M(sk1 packed) in A
    fft4096<-1>(C, B, tid);   // Z2 = DFT_M(sk2 packed) in C

    // ---- unpack rFFTs, multiply spectra, repack for inverse ----
    // X[k] = E[k] + W^k O[k]  where E=(Z[k]+conj(Z[M-k]))/2, O=-i(Z[k]-conj(Z[M-k]))/2
    // P = X[k],  Q = E - W^k O  => X[M-k] = conj(Q)
    // Y[k] = X1 X2 ; conj(Y[M-k]) = Q1 Q2
    // ZY[k]   = s*(G + iH), ZY[M-k] = s*conj(G - iH)
    //   G = (Yk + Q1Q2)/2, H = conj(W^k)*(Yk - Q1Q2)/2, s = 1/M  (irfft norm)
    const float scale = 1.0f / (float)FFT_M;
    for (int k = tid; k <= FFT_M/2; k += NTHREADS) {
        int mk = (FFT_M - k) & (FFT_M - 1);
        float2 z1k = A[k],  z1m = A[mk];
        float2 z2k = C[k],  z2m = C[mk];
        float sa, ca;
        __sincosf(-6.2831853071795864f * (float)k / (float)NREAL, &sa, &ca);
        float2 w = make_float2(ca, sa);            // W_N^k

        float2 E1  = make_float2(0.5f*(z1k.x + z1m.x), 0.5f*(z1k.y - z1m.y));
        float2 O1t = make_float2(0.5f*(z1k.x - z1m.x), 0.5f*(z1k.y + z1m.y));
        float2 O1  = make_float2(O1t.y, -O1t.x);   // -i * O1t
        float2 WO1 = cmul(w, O1);
        float2 P1  = cadd(E1, WO1);
        float2 Q1  = csub(E1, WO1);

        float2 E2  = make_float2(0.5f*(z2k.x + z2m.x), 0.5f*(z2k.y - z2m.y));
        float2 O2t = make_float2(0.5f*(z2k.x - z2m.x), 0.5f*(z2k.y + z2m.y));
        float2 O2  = make_float2(O2t.y, -O2t.x);
        float2 WO2 = cmul(w, O2);
        float2 P2  = cadd(E2, WO2);
        float2 Q2  = csub(E2, WO2);

        float2 Yk  = cmul(P1, P2);
        float2 Ymc = cmul(Q1, Q2);                 // conj(Y[M-k])
        float2 G   = make_float2(0.5f*(Yk.x + Ymc.x), 0.5f*(Yk.y + Ymc.y));
        float2 Hm  = make_float2(0.5f*(Yk.x - Ymc.x), 0.5f*(Yk.y - Ymc.y));
        float2 H   = cmul(make_float2(w.x, -w.y), Hm);

        B[k] = make_float2(scale*(G.x - H.y), scale*(G.y + H.x));
        if (k != 0 && k != FFT_M/2) {
            B[mk] = make_float2(scale*(G.x + H.y), scale*(H.x - G.y));
        }
    }
    __syncthreads();

    // ---- inverse FFT: y[2n] = Re, y[2n+1] = Im ----
    fft4096<1>(B, A, tid);

    // ---- LayerNorm over the 8192 reals ----
    float sum = 0.0f, sq = 0.0f;
    for (int n = tid; n < FFT_M; n += NTHREADS) {
        float2 v = B[n];
        sum += v.x + v.y;
        sq = fmaf(v.x, v.x, sq);
        sq = fmaf(v.y, v.y, sq);
    }
    #pragma unroll
    for (int o = 16; o; o >>= 1) {
        sum += __shfl_down_sync(0xffffffffu, sum, o);
        sq  += __shfl_down_sync(0xffffffffu, sq,  o);
    }
    const int wid = tid >> 5, lid = tid & 31;
    if (lid == 0) { rs[wid] = sum; rq[wid] = sq; }
    __syncthreads();
    if (wid == 0) {
        sum = (lid < 16) ? rs[lid] : 0.0f;
        sq  = (lid < 16) ? rq[lid] : 0.0f;
        #pragma unroll
        for (int o = 8; o; o >>= 1) {
            sum += __shfl_down_sync(0xffffffffu, sum, o);
            sq  += __shfl_down_sync(0xffffffffu, sq,  o);
        }
        if (lid == 0) { rs[0] = sum; rq[0] = sq; }
    }
    __syncthreads();
    const float mean = rs[0] * (1.0f / (float)NREAL);
    const float var  = rq[0] * (1.0f / (float)NREAL) - mean * mean;
    const float inv  = rsqrtf(var + 1e-5f);

    float2* orow = (float2*)(out + (size_t)b * NREAL);
    const float2* g2 = (const float2*)gamma;
    const float2* b2 = (const float2*)beta;
    for (int n = tid; n < FFT_M; n += NTHREADS) {
        float2 v  = B[n];
        float2 g  = g2[n];
        float2 be = b2[n];
        orow[n] = make_float2(fmaf((v.x - mean) * inv, g.x, be.x),
                              fmaf((v.y - mean) * inv, g.y, be.y));
    }
}

extern "C" void kernel_launch(void* const* d_in, const int* in_sizes, int n_in,
                              void* d_out, int out_size) {
    const float* img   = (const float*)d_in[0];
    const float* txt   = (const float*)d_in[1];
    const int*   h1    = (const int*)  d_in[2];
    const int*   h2    = (const int*)  d_in[3];
    const float* s1    = (const float*)d_in[4];
    const float* s2    = (const float*)d_in[5];
    const float* gamma = (const float*)d_in[6];
    const float* beta  = (const float*)d_in[7];
    float* out = (float*)d_out;

    const int batch = in_sizes[0] / IMG_DIM;
    const size_t smem = 3 * FFT_M * sizeof(float2);   // 96 KB
    cudaFuncSetAttribute(bilinear_fusion_kernel,
                         cudaFuncAttributeMaxDynamicSharedMemorySize, (int)smem);
    bilinear_fusion_kernel<<<batch, NTHREADS, smem>>>(
        img, txt, h1, h2, s1, s2, gamma, beta, out);
}